// round 10
// baseline (speedup 1.0000x reference)
#include <cuda_runtime.h>
#include <cstddef>

// Problem dims (fixed)
#define T_STEPS 128
#define BATCH   2048
#define IN0     18
#define H       256
#define G3      768   // 3*H
#define NB      16    // batch rows per block tile = rows per thread
#define NBLK    (BATCH / NB)   // 128 blocks
#define NTHR    256   // one thread per hidden unit j

typedef unsigned long long u64;

// ---------------- scratch ----------------
// gate-packed transposed weights: [k][j][4] (r, z, n, pad) -> one LDG.128 per (k,j)
__device__ float4 g_W4_hh0[H * H];   // [k*256 + j]
__device__ float4 g_W4_hh1[H * H];
__device__ float4 g_W4_ih1[H * H];
__device__ float g_xT[(size_t)T_STEPS * NBLK * IN0 * NB];  // x pre-transposed [t][blk][i][b]
__device__ float g_h2[BATCH * H];    // layer-1 final hidden, [b][c]

// ---------------- packed fp32x2 helpers ----------------
__device__ __forceinline__ u64 pk2(float a, float b) {
    u64 r; asm("mov.b64 %0, {%1, %2};" : "=l"(r) : "f"(a), "f"(b)); return r;
}
__device__ __forceinline__ void fma2(u64& d, u64 a, u64 b) {
    asm("fma.rn.f32x2 %0, %1, %2, %0;" : "+l"(d) : "l"(a), "l"(b));
}
__device__ __forceinline__ float2 up2(u64 p) {
    float2 f; asm("mov.b64 {%0, %1}, %2;" : "=f"(f.x), "=f"(f.y) : "l"(p)); return f;
}
__device__ __forceinline__ float sigf(float x) {
    return __fdividef(1.f, 1.f + __expf(-x));
}
__device__ __forceinline__ float tanhf_fast(float x) {
    return 2.f * sigf(2.f * x) - 1.f;
}

// ---------------- transpose [3H x H] -> packed [k][j][4] ----------------
__global__ void k_transpose(const float* __restrict__ src, int which) {
    float4* dstv = (which == 0) ? g_W4_hh0 : (which == 1) ? g_W4_hh1 : g_W4_ih1;
    float* dst = (float*)dstv;
    int idx = blockIdx.x * 256 + threadIdx.x;   // grid = 768 blocks -> H*768 threads
    int k = idx / G3;
    int rem = idx - k * G3;
    int g = rem >> 8;          // gate 0..2
    int j = rem & 255;
    dst[(k * 256 + j) * 4 + g] = src[(g * H + j) * H + k];
    if (g == 0) dst[(k * 256 + j) * 4 + 3] = 0.f;   // pad
}

// ---------------- pre-transpose x: [t][b][i] -> [t][blk][i][b16] ----------------
__global__ void k_xt(const float* __restrict__ x) {
    size_t idx = (size_t)blockIdx.x * 1024 + threadIdx.x;   // coalesced read side
    if (idx >= (size_t)T_STEPS * BATCH * IN0) return;
    int i = (int)(idx % IN0);
    size_t tb = idx / IN0;
    int b = (int)(tb % BATCH);
    int t = (int)(tb / BATCH);
    int blk = b >> 4, b16 = b & 15;
    g_xT[(((size_t)t * NBLK + blk) * IN0 + i) * NB + b16] = x[idx];
}

// fma a full 16-batch row (8 u64) against one gate weight into 8 accumulators
#define ROW_FMA(acc, wv)                                                     \
    do {                                                                     \
        fma2(acc[0], b0.x, wv); fma2(acc[1], b0.y, wv);                      \
        fma2(acc[2], b1.x, wv); fma2(acc[3], b1.y, wv);                      \
        fma2(acc[4], b2.x, wv); fma2(acc[5], b2.y, wv);                      \
        fma2(acc[6], b3.x, wv); fma2(acc[7], b3.y, wv);                      \
    } while (0)

// ---- pipelined single-matrix gemm (layer-0 hidden), chunk=8k double buffer ----
__device__ __forceinline__ void gemm_pipe1(const float4* __restrict__ W4,
                                           const float* __restrict__ sbuf,
                                           u64* __restrict__ ar, u64* __restrict__ az,
                                           u64* __restrict__ an, int j) {
    const float4* wp = W4 + j;     // stride per k = 256 float4
    float4 wb[2][8];
#pragma unroll
    for (int kk = 0; kk < 8; kk++) wb[0][kk] = __ldg(wp + kk * 256);
#pragma unroll 2
    for (int c = 0; c < H / 8; c++) {
        const int cur = c & 1, nxt = cur ^ 1;
        if (c + 1 < H / 8) {
#pragma unroll
            for (int kk = 0; kk < 8; kk++)
                wb[nxt][kk] = __ldg(wp + ((c + 1) * 8 + kk) * 256);
        }
#pragma unroll
        for (int kk = 0; kk < 8; kk++) {
            const int k = c * 8 + kk;
            float4 w = wb[cur][kk];
            u64 wr2 = pk2(w.x, w.x), wz2 = pk2(w.y, w.y), wn2 = pk2(w.z, w.z);
            const ulonglong2* hp = (const ulonglong2*)(sbuf + k * NB);
            ulonglong2 b0 = hp[0], b1 = hp[1], b2 = hp[2], b3 = hp[3];
            ROW_FMA(ar, wr2);
            ROW_FMA(az, wz2);
            ROW_FMA(an, wn2);
        }
    }
}

// ---- pipelined dual gemm (layer 1), chunk=4k double buffer ----
__device__ __forceinline__ void gemm_pipe2(const float4* __restrict__ W4i,
                                           const float4* __restrict__ W4h,
                                           const float* __restrict__ sxb,
                                           const float* __restrict__ shb,
                                           u64* __restrict__ ar, u64* __restrict__ az,
                                           u64* __restrict__ axn, u64* __restrict__ ahn,
                                           int j) {
    const float4* wpi = W4i + j;
    const float4* wph = W4h + j;
    float4 wb[2][4][2];   // [buf][kk][matrix: 0=input 1=hidden]
#pragma unroll
    for (int kk = 0; kk < 4; kk++) {
        wb[0][kk][0] = __ldg(wpi + kk * 256);
        wb[0][kk][1] = __ldg(wph + kk * 256);
    }
#pragma unroll 2
    for (int c = 0; c < H / 4; c++) {
        const int cur = c & 1, nxt = cur ^ 1;
        if (c + 1 < H / 4) {
#pragma unroll
            for (int kk = 0; kk < 4; kk++) {
                wb[nxt][kk][0] = __ldg(wpi + ((c + 1) * 4 + kk) * 256);
                wb[nxt][kk][1] = __ldg(wph + ((c + 1) * 4 + kk) * 256);
            }
        }
#pragma unroll
        for (int kk = 0; kk < 4; kk++) {
            const int k = c * 4 + kk;
            float4 wi = wb[cur][kk][0];
            float4 wh = wb[cur][kk][1];
            // input-side
            {
                u64 wr2 = pk2(wi.x, wi.x), wz2 = pk2(wi.y, wi.y), wn2 = pk2(wi.z, wi.z);
                const ulonglong2* xp = (const ulonglong2*)(sxb + k * NB);
                ulonglong2 b0 = xp[0], b1 = xp[1], b2 = xp[2], b3 = xp[3];
                ROW_FMA(ar, wr2);
                ROW_FMA(az, wz2);
                ROW_FMA(axn, wn2);
            }
            // hidden-side
            {
                u64 wr2 = pk2(wh.x, wh.x), wz2 = pk2(wh.y, wh.y), wn2 = pk2(wh.z, wh.z);
                const ulonglong2* hp = (const ulonglong2*)(shb + k * NB);
                ulonglong2 b0 = hp[0], b1 = hp[1], b2 = hp[2], b3 = hp[3];
                ROW_FMA(ar, wr2);
                ROW_FMA(az, wz2);
                ROW_FMA(ahn, wn2);
            }
        }
    }
}

// gates -> hnew[16]; old h read from smem slice (thread-private)
__device__ __forceinline__ void epilogue(u64* ar, u64* az, u64* axn, u64* ahn,
                                         const float* hold, float* hnew) {
#pragma unroll
    for (int p = 0; p < 8; p++) {
        float2 r2 = up2(ar[p]), z2 = up2(az[p]), x2 = up2(axn[p]), h2 = up2(ahn[p]);
        float r0 = sigf(r2.x), z0 = sigf(z2.x);
        float n0 = tanhf_fast(x2.x + r0 * h2.x);
        hnew[2 * p] = n0 + z0 * (hold[2 * p] - n0);
        float r1 = sigf(r2.y), z1 = sigf(z2.y);
        float n1 = tanhf_fast(x2.y + r1 * h2.y);
        hnew[2 * p + 1] = n1 + z1 * (hold[2 * p + 1] - n1);
    }
}

// ---------------- fused 2-layer GRU, persistent per batch tile ----------------
// Double-buffered state -> only 2 __syncthreads per timestep.
__global__ __launch_bounds__(NTHR, 1)
void k_gru(const float* __restrict__ Wih0,
           const float* __restrict__ bih0, const float* __restrict__ bhh0,
           const float* __restrict__ bih1, const float* __restrict__ bhh1) {
    extern __shared__ float smem[];
    float* sWih = smem;                       // [i][g], 18*768 = 13824
    float* sh0  = sWih + IN0 * G3;            // layer-0 h, 2 bufs x [c][b] (4096 each)
    float* sh1  = sh0 + 2 * H * NB;           // layer-1 h, 2 bufs
    float* sx   = sh1 + 2 * H * NB;           // x tile, 2 bufs x [i][b] (288 each)

    const int j = threadIdx.x;
    const int bbase = blockIdx.x * NB;
    const size_t xtile = (size_t)IN0 * NB;

    for (int idx = j; idx < IN0 * G3; idx += NTHR) {
        int i = idx / G3, g = idx - i * G3;
        sWih[idx] = Wih0[g * IN0 + i];
    }
    // zero buffer 0 of both states
    for (int idx = j; idx < H * NB; idx += NTHR) {
        sh0[idx] = 0.f;
        sh1[idx] = 0.f;
    }
    // stage x[0] into sx buffer 0 (clean copy from pre-transposed g_xT)
    {
        const float4* src = (const float4*)(g_xT + ((size_t)0 * NBLK + blockIdx.x) * xtile);
        float4* dst = (float4*)sx;
        for (int idx = j; idx < IN0 * NB / 4; idx += NTHR) dst[idx] = src[idx];
    }

    const float brz0 = bih0[j] + bhh0[j];
    const float bzz0 = bih0[H + j] + bhh0[H + j];
    const float bxn0 = bih0[2 * H + j];
    const float bhn0 = bhh0[2 * H + j];
    const float brz1 = bih1[j] + bhh1[j];
    const float bzz1 = bih1[H + j] + bhh1[H + j];
    const float bxn1 = bih1[2 * H + j];
    const float bhn1 = bhh1[2 * H + j];
    __syncthreads();

    for (int t = 0; t < T_STEPS; t++) {
        const int tc = t & 1, tn = tc ^ 1;
        const float* sh0c = sh0 + tc * (H * NB);
        float*       sh0n = sh0 + tn * (H * NB);
        const float* sh1c = sh1 + tc * (H * NB);
        float*       sh1n = sh1 + tn * (H * NB);
        const float* sxc  = sx + tc * (IN0 * NB);

        // ---------- layer 0 ----------
        u64 ar[8], az[8], axn[8], ahn[8];
#pragma unroll
        for (int p = 0; p < 8; p++) {
            ar[p] = pk2(brz0, brz0); az[p] = pk2(bzz0, bzz0);
            axn[p] = pk2(bxn0, bxn0); ahn[p] = pk2(bhn0, bhn0);
        }
        // input projection K=18 from smem
#pragma unroll
        for (int i = 0; i < IN0; i++) {
            float wr = sWih[i * G3 + j];
            float wz = sWih[i * G3 + H + j];
            float wn = sWih[i * G3 + 2 * H + j];
            u64 wr2 = pk2(wr, wr), wz2 = pk2(wz, wz), wn2 = pk2(wn, wn);
            const ulonglong2* xp = (const ulonglong2*)(sxc + i * NB);
            ulonglong2 b0 = xp[0], b1 = xp[1], b2 = xp[2], b3 = xp[3];
            ROW_FMA(ar, wr2);
            ROW_FMA(az, wz2);
            ROW_FMA(axn, wn2);
        }
        gemm_pipe1(g_W4_hh0, sh0c, ar, az, ahn, j);

        // epilogue writes to the OTHER buffer -> no barrier needed before it
        {
            float hnew[NB];
            epilogue(ar, az, axn, ahn, sh0c + j * NB, hnew);
            float4* w = (float4*)(sh0n + j * NB);
#pragma unroll
            for (int q = 0; q < 4; q++)
                w[q] = make_float4(hnew[4 * q], hnew[4 * q + 1],
                                   hnew[4 * q + 2], hnew[4 * q + 3]);
        }
        // stage x[t+1] into the other sx buffer (overlaps with other warps' epilogue)
        if (t + 1 < T_STEPS) {
            const float4* src =
                (const float4*)(g_xT + ((size_t)(t + 1) * NBLK + blockIdx.x) * xtile);
            float4* dst = (float4*)(sx + tn * (IN0 * NB));
            for (int idx = j; idx < IN0 * NB / 4; idx += NTHR) dst[idx] = src[idx];
        }
        __syncthreads();   // B1: sh0[tn] + sx[tn] visible to all

        // ---------- layer 1 (input = NEW h0) ----------
#pragma unroll
        for (int p = 0; p < 8; p++) {
            ar[p] = pk2(brz1, brz1); az[p] = pk2(bzz1, bzz1);
            axn[p] = pk2(bxn1, bxn1); ahn[p] = pk2(bhn1, bhn1);
        }
        gemm_pipe2(g_W4_ih1, g_W4_hh1, sh0n, sh1c, ar, az, axn, ahn, j);

        {
            float hnew[NB];
            epilogue(ar, az, axn, ahn, sh1c + j * NB, hnew);
            float4* w = (float4*)(sh1n + j * NB);
#pragma unroll
            for (int q = 0; q < 4; q++)
                w[q] = make_float4(hnew[4 * q], hnew[4 * q + 1],
                                   hnew[4 * q + 2], hnew[4 * q + 3]);
            if (t == T_STEPS - 1) {
#pragma unroll
                for (int b = 0; b < NB; b++)
                    g_h2[(size_t)(bbase + b) * H + j] = hnew[b];
            }
        }
        __syncthreads();   // B2: sh1[tn] visible before next step
    }
}

// ---------------- FC head ----------------
__global__ void k_fc(const float* __restrict__ fcw, const float* __restrict__ fcb,
                     float* __restrict__ out) {
    int warp = threadIdx.x >> 5, lane = threadIdx.x & 31;
    int row = blockIdx.x * 8 + warp;
    const float* h = &g_h2[(size_t)row * H];
    float a0 = 0.f, a1 = 0.f, a2 = 0.f, a3 = 0.f;
    for (int k = lane; k < H; k += 32) {
        float hv = h[k];
        a0 += hv * fcw[k];
        a1 += hv * fcw[H + k];
        a2 += hv * fcw[2 * H + k];
        a3 += hv * fcw[3 * H + k];
    }
#pragma unroll
    for (int off = 16; off; off >>= 1) {
        a0 += __shfl_xor_sync(0xffffffffu, a0, off);
        a1 += __shfl_xor_sync(0xffffffffu, a1, off);
        a2 += __shfl_xor_sync(0xffffffffu, a2, off);
        a3 += __shfl_xor_sync(0xffffffffu, a3, off);
    }
    if (lane == 0) {
        float l0 = a0 + fcb[0], l1 = a1 + fcb[1], l2 = a2 + fcb[2], l3 = a3 + fcb[3];
        out[row * 4 + 0] = 2.f / (1.f + expf(-l0)) - 1.f;
        out[row * 4 + 1] = 2.f / (1.f + expf(-l1)) - 1.f;
        out[row * 4 + 2] = 2.f / (1.f + expf(-l2)) - 1.f;
        out[row * 4 + 3] = 2.f / (1.f + expf(-l3)) - 1.f;
    }
}

extern "C" void kernel_launch(void* const* d_in, const int* in_sizes, int n_in,
                              void* d_out, int out_size) {
    const float* x    = (const float*)d_in[0];
    const float* Wih0 = (const float*)d_in[1];
    const float* Whh0 = (const float*)d_in[2];
    const float* bih0 = (const float*)d_in[3];
    const float* bhh0 = (const float*)d_in[4];
    const float* Wih1 = (const float*)d_in[5];
    const float* Whh1 = (const float*)d_in[6];
    const float* bih1 = (const float*)d_in[7];
    const float* bhh1 = (const float*)d_in[8];
    const float* fcw  = (const float*)d_in[9];
    const float* fcb  = (const float*)d_in[10];
    float* out = (float*)d_out;

    // floats: sWih 13824 + sh0 8192 + sh1 8192 + sx 576 = 30784 -> 123136 B
    const int gru_smem = (IN0 * G3 + 4 * H * NB + 2 * IN0 * NB) * (int)sizeof(float);
    static int smem_set = 0;
    if (!smem_set) {
        cudaFuncSetAttribute(k_gru, cudaFuncAttributeMaxDynamicSharedMemorySize, gru_smem);
        smem_set = 1;
    }

    k_xt<<<(int)(((size_t)T_STEPS * BATCH * IN0 + 1023) / 1024), 1024>>>(x);
    k_transpose<<<G3, 256>>>(Whh0, 0);
    k_transpose<<<G3, 256>>>(Whh1, 1);
    k_transpose<<<G3, 256>>>(Wih1, 2);
    k_gru<<<NBLK, NTHR, gru_smem>>>(Wih0, bih0, bhh0, bih1, bhh1);
    k_fc<<<BATCH / 8, 256>>>(fcw, fcb, out);
}

// round 11
// speedup vs baseline: 1.0975x; 1.0975x over previous
#include <cuda_runtime.h>
#include <cstddef>

// Problem dims (fixed)
#define T_STEPS 128
#define BATCH   2048
#define IN0     18
#define H       256
#define G3      768   // 3*H
#define NBR     14    // real batch rows per block tile (= rows per thread)
#define NBP     16    // padded row stride in smem/xT (keeps 16B alignment)
#define NBLKK   147   // 146 full tiles + 1 overlapping tail tile -> one wave on 148 SMs
#define NTHR    256   // one thread per hidden unit j

typedef unsigned long long u64;

// ---------------- scratch ----------------
// gate-packed transposed weights: [k][j][4] (r, z, n, pad) -> one LDG.128 per (k,j)
__device__ float4 g_W4_hh0[H * H];   // [k*256 + j]
__device__ float4 g_W4_hh1[H * H];
__device__ float4 g_W4_ih1[H * H];
__device__ float g_xT[(size_t)T_STEPS * NBLKK * IN0 * NBP];  // [t][blk][i][row16]
__device__ float g_h2[BATCH * H];    // layer-1 final hidden, [b][c]

__device__ __forceinline__ int blk_start(int blk) {
    return (blk < NBLKK - 1) ? NBR * blk : (BATCH - NBR);
}

// ---------------- packed fp32x2 helpers ----------------
__device__ __forceinline__ u64 pk2(float a, float b) {
    u64 r; asm("mov.b64 %0, {%1, %2};" : "=l"(r) : "f"(a), "f"(b)); return r;
}
__device__ __forceinline__ void fma2(u64& d, u64 a, u64 b) {
    asm("fma.rn.f32x2 %0, %1, %2, %0;" : "+l"(d) : "l"(a), "l"(b));
}
__device__ __forceinline__ float2 up2(u64 p) {
    float2 f; asm("mov.b64 {%0, %1}, %2;" : "=f"(f.x), "=f"(f.y) : "l"(p)); return f;
}
__device__ __forceinline__ float sigf(float x) {
    return __fdividef(1.f, 1.f + __expf(-x));
}
__device__ __forceinline__ float tanhf_fast(float x) {
    return 2.f * sigf(2.f * x) - 1.f;
}

// ---------------- transpose [3H x H] -> packed [k][j][4] ----------------
__global__ void k_transpose(const float* __restrict__ src, int which) {
    float4* dstv = (which == 0) ? g_W4_hh0 : (which == 1) ? g_W4_hh1 : g_W4_ih1;
    float* dst = (float*)dstv;
    int idx = blockIdx.x * 256 + threadIdx.x;   // grid = 768 blocks -> H*768 threads
    int k = idx / G3;
    int rem = idx - k * G3;
    int g = rem >> 8;          // gate 0..2
    int j = rem & 255;
    dst[(k * 256 + j) * 4 + g] = src[(g * H + j) * H + k];
    if (g == 0) dst[(k * 256 + j) * 4 + 3] = 0.f;   // pad
}

// ---------------- pre-transpose x: [t][b][i] -> [t][blk][i][row16] ----------------
__global__ void k_xt(const float* __restrict__ x) {
    size_t idx = (size_t)blockIdx.x * 256 + threadIdx.x;
    const size_t total = (size_t)T_STEPS * NBLKK * IN0 * NBR;
    if (idx >= total) return;
    int row = (int)(idx % NBR);
    size_t r1 = idx / NBR;
    int i = (int)(r1 % IN0);
    size_t r2 = r1 / IN0;
    int blk = (int)(r2 % NBLKK);
    int t = (int)(r2 / NBLKK);
    int b = blk_start(blk) + row;
    g_xT[(((size_t)t * NBLKK + blk) * IN0 + i) * NBP + row] =
        x[((size_t)t * BATCH + b) * IN0 + i];
}

// load one 14-wide padded row (7 u64) from ptr (16B-aligned, stride NBP floats)
#define LOAD_ROW(ptr, b0, b1, b2, b3v)                                       \
    ulonglong2 b0, b1, b2; u64 b3v;                                          \
    do {                                                                     \
        const ulonglong2* _hp = (const ulonglong2*)(ptr);                    \
        b0 = _hp[0]; b1 = _hp[1]; b2 = _hp[2];                               \
        b3v = ((const u64*)(ptr))[6];                                        \
    } while (0)

// fma a 14-batch row (7 u64) against one gate weight into 7 accumulators
#define ROW_FMA(acc, wv, b0, b1, b2, b3v)                                    \
    do {                                                                     \
        fma2(acc[0], b0.x, wv); fma2(acc[1], b0.y, wv);                      \
        fma2(acc[2], b1.x, wv); fma2(acc[3], b1.y, wv);                      \
        fma2(acc[4], b2.x, wv); fma2(acc[5], b2.y, wv);                      \
        fma2(acc[6], b3v, wv);                                               \
    } while (0)

// ---- pipelined single-matrix gemm (layer-0 hidden), chunk=8k double buffer ----
__device__ __forceinline__ void gemm_pipe1(const float4* __restrict__ W4,
                                           const float* __restrict__ sbuf,
                                           u64* __restrict__ ar, u64* __restrict__ az,
                                           u64* __restrict__ an, int j) {
    const float4* wp = W4 + j;     // stride per k = 256 float4
    float4 wb[2][8];
#pragma unroll
    for (int kk = 0; kk < 8; kk++) wb[0][kk] = __ldg(wp + kk * 256);
#pragma unroll 2
    for (int c = 0; c < H / 8; c++) {
        const int cur = c & 1, nxt = cur ^ 1;
        if (c + 1 < H / 8) {
#pragma unroll
            for (int kk = 0; kk < 8; kk++)
                wb[nxt][kk] = __ldg(wp + ((c + 1) * 8 + kk) * 256);
        }
#pragma unroll
        for (int kk = 0; kk < 8; kk++) {
            const int k = c * 8 + kk;
            float4 w = wb[cur][kk];
            u64 wr2 = pk2(w.x, w.x), wz2 = pk2(w.y, w.y), wn2 = pk2(w.z, w.z);
            LOAD_ROW(sbuf + k * NBP, b0, b1, b2, b3v);
            ROW_FMA(ar, wr2, b0, b1, b2, b3v);
            ROW_FMA(az, wz2, b0, b1, b2, b3v);
            ROW_FMA(an, wn2, b0, b1, b2, b3v);
        }
    }
}

// ---- pipelined dual gemm (layer 1), chunk=4k double buffer ----
__device__ __forceinline__ void gemm_pipe2(const float4* __restrict__ W4i,
                                           const float4* __restrict__ W4h,
                                           const float* __restrict__ sxb,
                                           const float* __restrict__ shb,
                                           u64* __restrict__ ar, u64* __restrict__ az,
                                           u64* __restrict__ axn, u64* __restrict__ ahn,
                                           int j) {
    const float4* wpi = W4i + j;
    const float4* wph = W4h + j;
    float4 wb[2][4][2];   // [buf][kk][matrix: 0=input 1=hidden]
#pragma unroll
    for (int kk = 0; kk < 4; kk++) {
        wb[0][kk][0] = __ldg(wpi + kk * 256);
        wb[0][kk][1] = __ldg(wph + kk * 256);
    }
#pragma unroll 2
    for (int c = 0; c < H / 4; c++) {
        const int cur = c & 1, nxt = cur ^ 1;
        if (c + 1 < H / 4) {
#pragma unroll
            for (int kk = 0; kk < 4; kk++) {
                wb[nxt][kk][0] = __ldg(wpi + ((c + 1) * 4 + kk) * 256);
                wb[nxt][kk][1] = __ldg(wph + ((c + 1) * 4 + kk) * 256);
            }
        }
#pragma unroll
        for (int kk = 0; kk < 4; kk++) {
            const int k = c * 4 + kk;
            float4 wi = wb[cur][kk][0];
            float4 wh = wb[cur][kk][1];
            // input-side
            {
                u64 wr2 = pk2(wi.x, wi.x), wz2 = pk2(wi.y, wi.y), wn2 = pk2(wi.z, wi.z);
                LOAD_ROW(sxb + k * NBP, b0, b1, b2, b3v);
                ROW_FMA(ar, wr2, b0, b1, b2, b3v);
                ROW_FMA(az, wz2, b0, b1, b2, b3v);
                ROW_FMA(axn, wn2, b0, b1, b2, b3v);
            }
            // hidden-side
            {
                u64 wr2 = pk2(wh.x, wh.x), wz2 = pk2(wh.y, wh.y), wn2 = pk2(wh.z, wh.z);
                LOAD_ROW(shb + k * NBP, b0, b1, b2, b3v);
                ROW_FMA(ar, wr2, b0, b1, b2, b3v);
                ROW_FMA(az, wz2, b0, b1, b2, b3v);
                ROW_FMA(ahn, wn2, b0, b1, b2, b3v);
            }
        }
    }
}

// gates -> hnew[14]; old h read from smem slice (thread-private)
__device__ __forceinline__ void epilogue(u64* ar, u64* az, u64* axn, u64* ahn,
                                         const float* hold, float* hnew) {
#pragma unroll
    for (int p = 0; p < 7; p++) {
        float2 r2 = up2(ar[p]), z2 = up2(az[p]), x2 = up2(axn[p]), h2 = up2(ahn[p]);
        float r0 = sigf(r2.x), z0 = sigf(z2.x);
        float n0 = tanhf_fast(x2.x + r0 * h2.x);
        hnew[2 * p] = n0 + z0 * (hold[2 * p] - n0);
        float r1 = sigf(r2.y), z1 = sigf(z2.y);
        float n1 = tanhf_fast(x2.y + r1 * h2.y);
        hnew[2 * p + 1] = n1 + z1 * (hold[2 * p + 1] - n1);
    }
}

// write hnew[14] to a padded row (3x float4 + 1x float2)
__device__ __forceinline__ void store_row(float* dst, const float* hnew) {
    float4* w4 = (float4*)dst;
    w4[0] = make_float4(hnew[0], hnew[1], hnew[2], hnew[3]);
    w4[1] = make_float4(hnew[4], hnew[5], hnew[6], hnew[7]);
    w4[2] = make_float4(hnew[8], hnew[9], hnew[10], hnew[11]);
    ((float2*)(dst + 12))[0] = make_float2(hnew[12], hnew[13]);
}

// ---------------- fused 2-layer GRU, persistent per batch tile ----------------
// Double-buffered state -> only 2 __syncthreads per timestep.
__global__ __launch_bounds__(NTHR, 1)
void k_gru(const float* __restrict__ Wih0,
           const float* __restrict__ bih0, const float* __restrict__ bhh0,
           const float* __restrict__ bih1, const float* __restrict__ bhh1) {
    extern __shared__ float smem[];
    float* sWih = smem;                       // [i][g], 18*768 = 13824
    float* sh0  = sWih + IN0 * G3;            // layer-0 h, 2 bufs x [c][row16]
    float* sh1  = sh0 + 2 * H * NBP;          // layer-1 h, 2 bufs
    float* sx   = sh1 + 2 * H * NBP;          // x tile, 2 bufs x [i][row16]

    const int j = threadIdx.x;
    const int bbase = blk_start(blockIdx.x);
    const size_t xtile = (size_t)IN0 * NBP;

    for (int idx = j; idx < IN0 * G3; idx += NTHR) {
        int i = idx / G3, g = idx - i * G3;
        sWih[idx] = Wih0[g * IN0 + i];
    }
    // zero buffer 0 of both states
    for (int idx = j; idx < H * NBP; idx += NTHR) {
        sh0[idx] = 0.f;
        sh1[idx] = 0.f;
    }
    // stage x[0] into sx buffer 0 (clean copy from pre-transposed g_xT)
    {
        const float4* src = (const float4*)(g_xT + ((size_t)0 * NBLKK + blockIdx.x) * xtile);
        float4* dst = (float4*)sx;
        for (int idx = j; idx < IN0 * NBP / 4; idx += NTHR) dst[idx] = src[idx];
    }

    const float brz0 = bih0[j] + bhh0[j];
    const float bzz0 = bih0[H + j] + bhh0[H + j];
    const float bxn0 = bih0[2 * H + j];
    const float bhn0 = bhh0[2 * H + j];
    const float brz1 = bih1[j] + bhh1[j];
    const float bzz1 = bih1[H + j] + bhh1[H + j];
    const float bxn1 = bih1[2 * H + j];
    const float bhn1 = bhh1[2 * H + j];
    __syncthreads();

    for (int t = 0; t < T_STEPS; t++) {
        const int tc = t & 1, tn = tc ^ 1;
        const float* sh0c = sh0 + tc * (H * NBP);
        float*       sh0n = sh0 + tn * (H * NBP);
        const float* sh1c = sh1 + tc * (H * NBP);
        float*       sh1n = sh1 + tn * (H * NBP);
        const float* sxc  = sx + tc * (IN0 * NBP);

        // ---------- layer 0 ----------
        u64 ar[7], az[7], axn[7], ahn[7];
#pragma unroll
        for (int p = 0; p < 7; p++) {
            ar[p] = pk2(brz0, brz0); az[p] = pk2(bzz0, bzz0);
            axn[p] = pk2(bxn0, bxn0); ahn[p] = pk2(bhn0, bhn0);
        }
        // input projection K=18 from smem
#pragma unroll
        for (int i = 0; i < IN0; i++) {
            float wr = sWih[i * G3 + j];
            float wz = sWih[i * G3 + H + j];
            float wn = sWih[i * G3 + 2 * H + j];
            u64 wr2 = pk2(wr, wr), wz2 = pk2(wz, wz), wn2 = pk2(wn, wn);
            LOAD_ROW(sxc + i * NBP, b0, b1, b2, b3v);
            ROW_FMA(ar, wr2, b0, b1, b2, b3v);
            ROW_FMA(az, wz2, b0, b1, b2, b3v);
            ROW_FMA(axn, wn2, b0, b1, b2, b3v);
        }
        gemm_pipe1(g_W4_hh0, sh0c, ar, az, ahn, j);

        // epilogue writes to the OTHER buffer -> no barrier needed before it
        {
            float hnew[NBR];
            epilogue(ar, az, axn, ahn, sh0c + j * NBP, hnew);
            store_row(sh0n + j * NBP, hnew);
        }
        // stage x[t+1] into the other sx buffer (overlaps with other warps' epilogue)
        if (t + 1 < T_STEPS) {
            const float4* src =
                (const float4*)(g_xT + ((size_t)(t + 1) * NBLKK + blockIdx.x) * xtile);
            float4* dst = (float4*)(sx + tn * (IN0 * NBP));
            for (int idx = j; idx < IN0 * NBP / 4; idx += NTHR) dst[idx] = src[idx];
        }
        __syncthreads();   // B1: sh0[tn] + sx[tn] visible to all

        // ---------- layer 1 (input = NEW h0) ----------
#pragma unroll
        for (int p = 0; p < 7; p++) {
            ar[p] = pk2(brz1, brz1); az[p] = pk2(bzz1, bzz1);
            axn[p] = pk2(bxn1, bxn1); ahn[p] = pk2(bhn1, bhn1);
        }
        gemm_pipe2(g_W4_ih1, g_W4_hh1, sh0n, sh1c, ar, az, axn, ahn, j);

        {
            float hnew[NBR];
            epilogue(ar, az, axn, ahn, sh1c + j * NBP, hnew);
            store_row(sh1n + j * NBP, hnew);
            if (t == T_STEPS - 1) {
#pragma unroll
                for (int b = 0; b < NBR; b++)
                    g_h2[(size_t)(bbase + b) * H + j] = hnew[b];
            }
        }
        __syncthreads();   // B2: sh1[tn] visible before next step
    }
}

// ---------------- FC head ----------------
__global__ void k_fc(const float* __restrict__ fcw, const float* __restrict__ fcb,
                     float* __restrict__ out) {
    int warp = threadIdx.x >> 5, lane = threadIdx.x & 31;
    int row = blockIdx.x * 8 + warp;
    const float* h = &g_h2[(size_t)row * H];
    float a0 = 0.f, a1 = 0.f, a2 = 0.f, a3 = 0.f;
    for (int k = lane; k < H; k += 32) {
        float hv = h[k];
        a0 += hv * fcw[k];
        a1 += hv * fcw[H + k];
        a2 += hv * fcw[2 * H + k];
        a3 += hv * fcw[3 * H + k];
    }
#pragma unroll
    for (int off = 16; off; off >>= 1) {
        a0 += __shfl_xor_sync(0xffffffffu, a0, off);
        a1 += __shfl_xor_sync(0xffffffffu, a1, off);
        a2 += __shfl_xor_sync(0xffffffffu, a2, off);
        a3 += __shfl_xor_sync(0xffffffffu, a3, off);
    }
    if (lane == 0) {
        float l0 = a0 + fcb[0], l1 = a1 + fcb[1], l2 = a2 + fcb[2], l3 = a3 + fcb[3];
        out[row * 4 + 0] = 2.f / (1.f + expf(-l0)) - 1.f;
        out[row * 4 + 1] = 2.f / (1.f + expf(-l1)) - 1.f;
        out[row * 4 + 2] = 2.f / (1.f + expf(-l2)) - 1.f;
        out[row * 4 + 3] = 2.f / (1.f + expf(-l3)) - 1.f;
    }
}

extern "C" void kernel_launch(void* const* d_in, const int* in_sizes, int n_in,
                              void* d_out, int out_size) {
    const float* x    = (const float*)d_in[0];
    const float* Wih0 = (const float*)d_in[1];
    const float* Whh0 = (const float*)d_in[2];
    const float* bih0 = (const float*)d_in[3];
    const float* bhh0 = (const float*)d_in[4];
    const float* Wih1 = (const float*)d_in[5];
    const float* Whh1 = (const float*)d_in[6];
    const float* bih1 = (const float*)d_in[7];
    const float* bhh1 = (const float*)d_in[8];
    const float* fcw  = (const float*)d_in[9];
    const float* fcb  = (const float*)d_in[10];
    float* out = (float*)d_out;

    // floats: sWih 13824 + sh0 8192 + sh1 8192 + sx 576 = 30784 -> 123136 B
    const int gru_smem = (IN0 * G3 + 4 * H * NBP + 2 * IN0 * NBP) * (int)sizeof(float);
    static int smem_set = 0;
    if (!smem_set) {
        cudaFuncSetAttribute(k_gru, cudaFuncAttributeMaxDynamicSharedMemorySize, gru_smem);
        smem_set = 1;
    }

    {
        const size_t total = (size_t)T_STEPS * NBLKK * IN0 * NBR;
        k_xt<<<(int)((total + 255) / 256), 256>>>(x);
    }
    k_transpose<<<G3, 256>>>(Whh0, 0);
    k_transpose<<<G3, 256>>>(Whh1, 1);
    k_transpose<<<G3, 256>>>(Wih1, 2);
    k_gru<<<NBLKK, NTHR, gru_smem>>>(Wih0, bih0, bhh0, bih1, bhh1);
    k_fc<<<BATCH / 8, 256>>>(fcw, fcb, out);
}